// round 15
// baseline (speedup 1.0000x reference)
#include <cuda_runtime.h>
#include <cuda_fp16.h>

// ----------------------------------------------------------------------------
// SymplecticGyroceptron — R15: R14 tensor-core path + latency/occupancy fix.
//
// R14 measured: tensor 42.7%, issue 42.3%, occ 23.8% (regs=121, 16 warps/SM).
// Floors all ~350us (tensor 357, MUFU 333, issue-work 354) -> pure latency
// problem. Fixes (datapath numerics byte-identical to verified R14):
//   1. GEMM2 accumulators split into independent hi/lo chains (split-precision
//      s-dim): serial mma depth 8 -> 4; 4 independent chains.
//   2. Bg fragments live in SHARED, one uint4 per (l,kt,idx2) =
//      (s0rr0,s0rr1,s1rr0,s1rr1): 4 predicated LDS.128 per grad call,
//      frees 16 registers.
//   3. launch_bounds(128,5) -> 102-reg cap, 20 warps/SM.
// ----------------------------------------------------------------------------

#define NLAYERS 16   // 0..7 = psi (eps=1), 8..15 = ni (eps=0.01)
#define TPB 128

typedef unsigned int u32;

__device__ u32    g_B1[NLAYERS * 8 * 16];   // [l][j(ntile)][idx=q*8+c]
__device__ uint4  g_Bg[NLAYERS * 4 * 8];    // [l][kt][idx2] -> (s0rr0,s0rr1,s1rr0,s1rr1)
__device__ float2 g_eta[NLAYERS];
__device__ float2 g_cs;

__device__ __forceinline__ u32 f2h2(float lo, float hi) {
    u32 d; asm("cvt.rn.f16x2.f32 %0, %1, %2;" : "=r"(d) : "f"(hi), "f"(lo));
    return d;   // lo operand -> low half (element 0)
}

__global__ void prep_kernel(const float* __restrict__ theta0,
                            const float* __restrict__ psi_Win,
                            const float* __restrict__ psi_Wout,
                            const float* __restrict__ psi_b,
                            const float* __restrict__ psi_eta,
                            const float* __restrict__ ni_Win,
                            const float* __restrict__ ni_Wout,
                            const float* __restrict__ ni_b,
                            const float* __restrict__ ni_eta)
{
    int t = threadIdx.x;

    // ---- B1 table (GEMM1 B fragments): identical to verified R14 ----
    for (int e = t; e < NLAYERS * 8 * 16; e += blockDim.x) {
        int l = e >> 7;
        int rem = e & 127;
        int j = rem >> 4, idx = rem & 15;
        int q = idx >> 3, c = idx & 7;
        int n = j * 8 + c;
        const float *Win, *b; int i;
        if (l < 8) { i = l;     Win = psi_Win; b = psi_b; }
        else       { i = l - 8; Win = ni_Win;  b = ni_b;  }
        float wx = Win[i * 128 + n];
        float wy = Win[i * 128 + 64 + n];
        float bb = b[i * 64 + n];
        u32 v;
        if (q == 0) {
            u32 hx = (u32)__half_as_ushort(__float2half_rn(wx));
            u32 hy = (u32)__half_as_ushort(__float2half_rn(wy));
            v = (hy << 16) | hx;
        } else {
            v = (u32)__half_as_ushort(__float2half_rn(bb));
        }
        g_B1[e] = v;
    }

    // ---- Bg table, uint4-packed: 512 entries ----
    for (int e = t; e < NLAYERS * 4 * 8; e += blockDim.x) {
        int idx2 = e & 7;
        int kt = (e >> 3) & 3;
        int l  = e >> 5;
        int q = idx2 >> 1, nn = idx2 & 1;
        const float *Win, *Wout; float eps; int i;
        if (l < 8) { i = l;     Win = psi_Win; Wout = psi_Wout; eps = 1.0f;  }
        else       { i = l - 8; Win = ni_Win;  Wout = ni_Wout;  eps = 0.01f; }
        u32 packed[2][2];   // [s][rr]
#pragma unroll
        for (int rr = 0; rr < 2; ++rr) {
            int k = kt * 16 + rr * 8 + q * 2;
            float w0 = Win[i * 128 + (nn ? 64 : 0) + k];
            float w1 = Win[i * 128 + (nn ? 64 : 0) + k + 1];
            float v0 = -Wout[i * 64 + k]     * eps * w0;   // negated: t^2-1 trick
            float v1 = -Wout[i * 64 + k + 1] * eps * w1;
            __half h0 = __float2half_rn(v0), h1 = __float2half_rn(v1);
            __half r0 = __float2half_rn(v0 - __half2float(h0));
            __half r1 = __float2half_rn(v1 - __half2float(h1));
            packed[0][rr] = ((u32)__half_as_ushort(h1) << 16) | (u32)__half_as_ushort(h0);
            packed[1][rr] = ((u32)__half_as_ushort(r1) << 16) | (u32)__half_as_ushort(r0);
        }
        uint4 v;
        v.x = packed[0][0]; v.y = packed[0][1];
        v.z = packed[1][0]; v.w = packed[1][1];
        g_Bg[e] = v;
    }

    if (t < NLAYERS) {
        const float* e2 = (t < 8) ? (psi_eta + t * 2) : (ni_eta + (t - 8) * 2);
        g_eta[t] = make_float2(e2[0], e2[1]);
    }
    if (t == 0) {
        float th = theta0[0];
        g_cs = make_float2(cosf(th), sinf(th));
    }
}

// grad_V for 32 points via back-to-back mma. Split-precision GEMM2 runs as
// two INDEPENDENT accumulator chains (hi/lo), summed at the end.
__device__ __forceinline__ void grad_mma(const u32 B1[8],
                                         const uint4* __restrict__ sBgL,
                                         bool hasBg, int idx2,
                                         const float yn0[4], const float yn1[4],
                                         bool own, u32 aconst,
                                         float G0[4], float G1[4])
{
    u32 A1[2][2];
#pragma unroll
    for (int mt = 0; mt < 2; ++mt) {
        u32 v0 = f2h2(yn0[2 * mt],     yn1[2 * mt]);
        u32 v1 = f2h2(yn0[2 * mt + 1], yn1[2 * mt + 1]);
        A1[mt][0] = own ? v0 : aconst;
        A1[mt][1] = own ? v1 : aconst;
    }
    float Chi[2][4] = {{0.f,0.f,0.f,0.f},{0.f,0.f,0.f,0.f}};
    float Clo[2][4] = {{0.f,0.f,0.f,0.f},{0.f,0.f,0.f,0.f}};
    const u32 NEG1H = 0xBC00BC00u;   // h2(-1,-1)
#pragma unroll
    for (int kt = 0; kt < 4; ++kt) {
        uint4 bg = hasBg ? sBgL[kt * 8 + idx2] : make_uint4(0u, 0u, 0u, 0u);
        u32 A2[2][4];
#pragma unroll
        for (int jj = 0; jj < 2; ++jj) {
            u32 b1 = B1[kt * 2 + jj];
#pragma unroll
            for (int mt = 0; mt < 2; ++mt) {
                float c0 = 0.f, c1 = 0.f, c2 = 0.f, c3 = 0.f;
                asm("mma.sync.aligned.m16n8k8.row.col.f32.f16.f16.f32 "
                    "{%0,%1,%2,%3}, {%4,%5}, {%6}, {%0,%1,%2,%3};"
                    : "+f"(c0), "+f"(c1), "+f"(c2), "+f"(c3)
                    : "r"(A1[mt][0]), "r"(A1[mt][1]), "r"(b1));
                u32 h0 = f2h2(c0, c1);
                u32 h1 = f2h2(c2, c3);
                asm("tanh.approx.f16x2 %0, %0;" : "+r"(h0));
                asm("tanh.approx.f16x2 %0, %0;" : "+r"(h1));
                u32 m0, m1;
                asm("fma.rn.f16x2 %0, %1, %1, %2;" : "=r"(m0) : "r"(h0), "r"(NEG1H));
                asm("fma.rn.f16x2 %0, %1, %1, %2;" : "=r"(m1) : "r"(h1), "r"(NEG1H));
                A2[mt][jj * 2]     = m0;   // C-frag == A-frag identity
                A2[mt][jj * 2 + 1] = m1;
            }
        }
#pragma unroll
        for (int mt = 0; mt < 2; ++mt) {
            asm("mma.sync.aligned.m16n8k16.row.col.f32.f16.f16.f32 "
                "{%0,%1,%2,%3}, {%4,%5,%6,%7}, {%8,%9}, {%0,%1,%2,%3};"
                : "+f"(Chi[mt][0]), "+f"(Chi[mt][1]),
                  "+f"(Chi[mt][2]), "+f"(Chi[mt][3])
                : "r"(A2[mt][0]), "r"(A2[mt][1]), "r"(A2[mt][2]), "r"(A2[mt][3]),
                  "r"(bg.x), "r"(bg.y));
            asm("mma.sync.aligned.m16n8k16.row.col.f32.f16.f16.f32 "
                "{%0,%1,%2,%3}, {%4,%5,%6,%7}, {%8,%9}, {%0,%1,%2,%3};"
                : "+f"(Clo[mt][0]), "+f"(Clo[mt][1]),
                  "+f"(Clo[mt][2]), "+f"(Clo[mt][3])
                : "r"(A2[mt][0]), "r"(A2[mt][1]), "r"(A2[mt][2]), "r"(A2[mt][3]),
                  "r"(bg.z), "r"(bg.w));
        }
    }
#pragma unroll
    for (int mt = 0; mt < 2; ++mt) {
        G0[2 * mt]     = Chi[mt][0] + Clo[mt][0];
        G1[2 * mt]     = Chi[mt][1] + Clo[mt][1];
        G0[2 * mt + 1] = Chi[mt][2] + Clo[mt][2];
        G1[2 * mt + 1] = Chi[mt][3] + Clo[mt][3];
    }
}

__global__ void __launch_bounds__(TPB, 5)
gyro_kernel(const float4* __restrict__ rin, float4* __restrict__ out,
            int B, int nWarps)
{
    __shared__ u32    sB1[NLAYERS * 8 * 16];
    __shared__ uint4  sBg[NLAYERS * 4 * 8];
    __shared__ float2 seta[NLAYERS];
    __shared__ float2 scs;

    for (int i = threadIdx.x; i < NLAYERS * 8 * 16; i += TPB) sB1[i] = g_B1[i];
    for (int i = threadIdx.x; i < NLAYERS * 4 * 8; i += TPB)  sBg[i] = g_Bg[i];
    if (threadIdx.x < NLAYERS) seta[threadIdx.x] = g_eta[threadIdx.x];
    if (threadIdx.x == 0)      scs = g_cs;
    __syncthreads();

    int wid = blockIdx.x * (TPB / 32) + (threadIdx.x >> 5);
    if (wid >= nWarps) return;
    int lane = threadIdx.x & 31;
    int base = wid * 32;
    int r = lane >> 2;
    int q = lane & 3;
    bool own = (q == 0);
    u32 aconst = (q == 1) ? 0x00003C00u : 0u;   // h2(1,0) bias row
    bool hasBg = (r < 2);
    int idx2 = q * 2 + (r & 1);                  // valid when hasBg

    float x0[4] = {0,0,0,0}, x1[4] = {0,0,0,0};
    float y0[4] = {0,0,0,0}, y1[4] = {0,0,0,0};
    if (own) {
#pragma unroll
        for (int i = 0; i < 4; ++i) {
            int p = base + r + i * 8;
            if (p < B) {
                float4 z = rin[p];
                x0[i] = z.x; x1[i] = z.y; y0[i] = z.z; y1[i] = z.w;
            }
        }
    }

    u32 B1f[8];

    // ---- inverse psi layers, l = 7 .. 0 ----
    for (int l = 7; l >= 0; --l) {
        {   // load B1 fragment for this layer
            bool hasB1 = (q < 2);
            int i1 = (l * 8) * 16 + q * 8 + r;
#pragma unroll
            for (int j = 0; j < 8; ++j)
                B1f[j] = hasB1 ? sB1[i1 + j * 16] : 0u;
        }
        const uint4* sBgL = &sBg[l * 4 * 8];
        float e0 = seta[l].x, e1 = seta[l].y;
#pragma unroll 1
        for (int k = 0; k < 4; ++k) {
            float yn0[4], yn1[4], G0[4], G1[4];
#pragma unroll
            for (int i = 0; i < 4; ++i) { yn0[i] = x0[i] - e0; yn1[i] = x1[i] - e1; }
            grad_mma(B1f, sBgL, hasBg, idx2, yn0, yn1, own, aconst, G0, G1);
#pragma unroll
            for (int i = 0; i < 4; ++i) {
                float nx0 = G0[i] - y0[i], nx1 = G1[i] - y1[i];
                y0[i] = yn0[i]; y1[i] = yn1[i];
                x0[i] = nx0;    x1[i] = nx1;
            }
        }
    }

    // ---- circle action ----
    {
        float c = scs.x, s = scs.y;
#pragma unroll
        for (int i = 0; i < 4; ++i) {
            float q1 = x0[i], p1 = y0[i];
            x0[i] = fmaf(c, q1, s * p1);
            y0[i] = fmaf(c, p1, -s * q1);
        }
    }

    // ---- forward layers: l = 0..7 psi, l = 8..15 ni ----
    for (int l = 0; l < NLAYERS; ++l) {
        {
            bool hasB1 = (q < 2);
            int i1 = (l * 8) * 16 + q * 8 + r;
#pragma unroll
            for (int j = 0; j < 8; ++j)
                B1f[j] = hasB1 ? sB1[i1 + j * 16] : 0u;
        }
        const uint4* sBgL = &sBg[l * 4 * 8];
        float e0 = seta[l].x, e1 = seta[l].y;
#pragma unroll 1
        for (int k = 0; k < 4; ++k) {
            float G0[4], G1[4];
            grad_mma(B1f, sBgL, hasBg, idx2, y0, y1, own, aconst, G0, G1);
#pragma unroll
            for (int i = 0; i < 4; ++i) {
                float nx0 = y0[i] + e0, nx1 = y1[i] + e1;
                float ny0 = G0[i] - x0[i], ny1 = G1[i] - x1[i];
                x0[i] = nx0; x1[i] = nx1;
                y0[i] = ny0; y1[i] = ny1;
            }
        }
    }

    if (own) {
#pragma unroll
        for (int i = 0; i < 4; ++i) {
            int p = base + r + i * 8;
            if (p < B)
                out[p] = make_float4(x0[i], x1[i], y0[i], y1[i]);
        }
    }
}

extern "C" void kernel_launch(void* const* d_in, const int* in_sizes, int n_in,
                              void* d_out, int out_size)
{
    const float* r        = (const float*)d_in[0];
    const float* theta0   = (const float*)d_in[1];
    const float* psi_Win  = (const float*)d_in[2];
    const float* psi_Wout = (const float*)d_in[3];
    const float* psi_b    = (const float*)d_in[4];
    const float* psi_eta  = (const float*)d_in[5];
    const float* ni_Win   = (const float*)d_in[6];
    const float* ni_Wout  = (const float*)d_in[7];
    const float* ni_b     = (const float*)d_in[8];
    const float* ni_eta   = (const float*)d_in[9];

    int B = in_sizes[0] / 4;
    int nWarps = (B + 31) / 32;

    prep_kernel<<<1, 1024>>>(theta0, psi_Win, psi_Wout, psi_b, psi_eta,
                             ni_Win, ni_Wout, ni_b, ni_eta);

    int blocks = (nWarps + (TPB / 32) - 1) / (TPB / 32);
    gyro_kernel<<<blocks, TPB>>>((const float4*)r, (float4*)d_out, B, nWarps);
}

// round 16
// speedup vs baseline: 1.0250x; 1.0250x over previous
#include <cuda_runtime.h>
#include <cuda_fp16.h>

// ----------------------------------------------------------------------------
// SymplecticGyroceptron — R16: MMA path, shallow accumulator chains + occupancy.
//
// R15 diagnosis: dur = issue_work(372us)/eff(0.44); per-substep critical path
// ~3000 cyc (mma1 -> elementwise -> 4-deep mma2 chain), latency-bound.
// Changes vs R15 (datapath/fragment layout otherwise identical):
//   1. GEMM2 split-precision DROPPED: 24 mma/substep (was 32), Wg single f16.
//   2. 4 independent GEMM2 accumulator chains [mt][kt&1] -> serial depth 2.
//   3. launch_bounds(128,6): 85-reg cap -> 24 warps/SM.
// ----------------------------------------------------------------------------

#define NLAYERS 16   // 0..7 = psi (eps=1), 8..15 = ni (eps=0.01)
#define TPB 128

typedef unsigned int u32;

__device__ u32    g_B1[NLAYERS * 8 * 16];   // [l][j(ntile)][idx=q*8+c]
__device__ uint2  g_Bg[NLAYERS * 4 * 8];    // [l][kt][idx2] -> (rr0, rr1)
__device__ float2 g_eta[NLAYERS];
__device__ float2 g_cs;

__device__ __forceinline__ u32 f2h2(float lo, float hi) {
    u32 d; asm("cvt.rn.f16x2.f32 %0, %1, %2;" : "=r"(d) : "f"(hi), "f"(lo));
    return d;   // lo operand -> low half (element 0)
}

__global__ void prep_kernel(const float* __restrict__ theta0,
                            const float* __restrict__ psi_Win,
                            const float* __restrict__ psi_Wout,
                            const float* __restrict__ psi_b,
                            const float* __restrict__ psi_eta,
                            const float* __restrict__ ni_Win,
                            const float* __restrict__ ni_Wout,
                            const float* __restrict__ ni_b,
                            const float* __restrict__ ni_eta)
{
    int t = threadIdx.x;

    // ---- B1 table (GEMM1 B fragments): identical to verified R14/R15 ----
    for (int e = t; e < NLAYERS * 8 * 16; e += blockDim.x) {
        int l = e >> 7;
        int rem = e & 127;
        int j = rem >> 4, idx = rem & 15;
        int q = idx >> 3, c = idx & 7;
        int n = j * 8 + c;
        const float *Win, *b; int i;
        if (l < 8) { i = l;     Win = psi_Win; b = psi_b; }
        else       { i = l - 8; Win = ni_Win;  b = ni_b;  }
        float wx = Win[i * 128 + n];
        float wy = Win[i * 128 + 64 + n];
        float bb = b[i * 64 + n];
        u32 v;
        if (q == 0) {
            u32 hx = (u32)__half_as_ushort(__float2half_rn(wx));
            u32 hy = (u32)__half_as_ushort(__float2half_rn(wy));
            v = (hy << 16) | hx;
        } else {
            v = (u32)__half_as_ushort(__float2half_rn(bb));
        }
        g_B1[e] = v;
    }

    // ---- Bg table (single-precision f16, uint2-packed): 512 entries ----
    for (int e = t; e < NLAYERS * 4 * 8; e += blockDim.x) {
        int idx2 = e & 7;
        int kt = (e >> 3) & 3;
        int l  = e >> 5;
        int q = idx2 >> 1, nn = idx2 & 1;
        const float *Win, *Wout; float eps; int i;
        if (l < 8) { i = l;     Win = psi_Win; Wout = psi_Wout; eps = 1.0f;  }
        else       { i = l - 8; Win = ni_Win;  Wout = ni_Wout;  eps = 0.01f; }
        u32 packed[2];   // [rr]
#pragma unroll
        for (int rr = 0; rr < 2; ++rr) {
            int k = kt * 16 + rr * 8 + q * 2;
            float w0 = Win[i * 128 + (nn ? 64 : 0) + k];
            float w1 = Win[i * 128 + (nn ? 64 : 0) + k + 1];
            float v0 = -Wout[i * 64 + k]     * eps * w0;   // negated: t^2-1 trick
            float v1 = -Wout[i * 64 + k + 1] * eps * w1;
            __half h0 = __float2half_rn(v0), h1 = __float2half_rn(v1);
            packed[rr] = ((u32)__half_as_ushort(h1) << 16) | (u32)__half_as_ushort(h0);
        }
        g_Bg[e] = make_uint2(packed[0], packed[1]);
    }

    if (t < NLAYERS) {
        const float* e2 = (t < 8) ? (psi_eta + t * 2) : (ni_eta + (t - 8) * 2);
        g_eta[t] = make_float2(e2[0], e2[1]);
    }
    if (t == 0) {
        float th = theta0[0];
        g_cs = make_float2(cosf(th), sinf(th));
    }
}

// grad_V for 32 points via back-to-back mma. GEMM2 accumulates into 4
// independent chains [mt][kt&1] (serial depth 2), summed at the end.
__device__ __forceinline__ void grad_mma(const u32 B1[8],
                                         const uint2* __restrict__ sBgL,
                                         bool hasBg, int idx2,
                                         const float yn0[4], const float yn1[4],
                                         bool own, u32 aconst,
                                         float G0[4], float G1[4])
{
    u32 A1[2][2];
#pragma unroll
    for (int mt = 0; mt < 2; ++mt) {
        u32 v0 = f2h2(yn0[2 * mt],     yn1[2 * mt]);
        u32 v1 = f2h2(yn0[2 * mt + 1], yn1[2 * mt + 1]);
        A1[mt][0] = own ? v0 : aconst;
        A1[mt][1] = own ? v1 : aconst;
    }
    float C[2][2][4] = {{{0.f,0.f,0.f,0.f},{0.f,0.f,0.f,0.f}},
                        {{0.f,0.f,0.f,0.f},{0.f,0.f,0.f,0.f}}};
    const u32 NEG1H = 0xBC00BC00u;   // h2(-1,-1)
#pragma unroll
    for (int kt = 0; kt < 4; ++kt) {
        uint2 bg = hasBg ? sBgL[kt * 8 + idx2] : make_uint2(0u, 0u);
        u32 A2[2][4];
#pragma unroll
        for (int jj = 0; jj < 2; ++jj) {
            u32 b1 = B1[kt * 2 + jj];
#pragma unroll
            for (int mt = 0; mt < 2; ++mt) {
                float c0 = 0.f, c1 = 0.f, c2 = 0.f, c3 = 0.f;
                asm("mma.sync.aligned.m16n8k8.row.col.f32.f16.f16.f32 "
                    "{%0,%1,%2,%3}, {%4,%5}, {%6}, {%0,%1,%2,%3};"
                    : "+f"(c0), "+f"(c1), "+f"(c2), "+f"(c3)
                    : "r"(A1[mt][0]), "r"(A1[mt][1]), "r"(b1));
                u32 h0 = f2h2(c0, c1);
                u32 h1 = f2h2(c2, c3);
                asm("tanh.approx.f16x2 %0, %0;" : "+r"(h0));
                asm("tanh.approx.f16x2 %0, %0;" : "+r"(h1));
                u32 m0, m1;
                asm("fma.rn.f16x2 %0, %1, %1, %2;" : "=r"(m0) : "r"(h0), "r"(NEG1H));
                asm("fma.rn.f16x2 %0, %1, %1, %2;" : "=r"(m1) : "r"(h1), "r"(NEG1H));
                A2[mt][jj * 2]     = m0;   // C-frag == A-frag identity
                A2[mt][jj * 2 + 1] = m1;
            }
        }
        int par = kt & 1;
#pragma unroll
        for (int mt = 0; mt < 2; ++mt) {
            asm("mma.sync.aligned.m16n8k16.row.col.f32.f16.f16.f32 "
                "{%0,%1,%2,%3}, {%4,%5,%6,%7}, {%8,%9}, {%0,%1,%2,%3};"
                : "+f"(C[mt][par][0]), "+f"(C[mt][par][1]),
                  "+f"(C[mt][par][2]), "+f"(C[mt][par][3])
                : "r"(A2[mt][0]), "r"(A2[mt][1]), "r"(A2[mt][2]), "r"(A2[mt][3]),
                  "r"(bg.x), "r"(bg.y));
        }
    }
#pragma unroll
    for (int mt = 0; mt < 2; ++mt) {
        G0[2 * mt]     = C[mt][0][0] + C[mt][1][0];
        G1[2 * mt]     = C[mt][0][1] + C[mt][1][1];
        G0[2 * mt + 1] = C[mt][0][2] + C[mt][1][2];
        G1[2 * mt + 1] = C[mt][0][3] + C[mt][1][3];
    }
}

__global__ void __launch_bounds__(TPB, 6)
gyro_kernel(const float4* __restrict__ rin, float4* __restrict__ out,
            int B, int nWarps)
{
    __shared__ u32    sB1[NLAYERS * 8 * 16];
    __shared__ uint2  sBg[NLAYERS * 4 * 8];
    __shared__ float2 seta[NLAYERS];
    __shared__ float2 scs;

    for (int i = threadIdx.x; i < NLAYERS * 8 * 16; i += TPB) sB1[i] = g_B1[i];
    for (int i = threadIdx.x; i < NLAYERS * 4 * 8; i += TPB)  sBg[i] = g_Bg[i];
    if (threadIdx.x < NLAYERS) seta[threadIdx.x] = g_eta[threadIdx.x];
    if (threadIdx.x == 0)      scs = g_cs;
    __syncthreads();

    int wid = blockIdx.x * (TPB / 32) + (threadIdx.x >> 5);
    if (wid >= nWarps) return;
    int lane = threadIdx.x & 31;
    int base = wid * 32;
    int r = lane >> 2;
    int q = lane & 3;
    bool own = (q == 0);
    u32 aconst = (q == 1) ? 0x00003C00u : 0u;   // h2(1,0) bias row
    bool hasBg = (r < 2);
    int idx2 = q * 2 + (r & 1);                  // valid when hasBg

    float x0[4] = {0,0,0,0}, x1[4] = {0,0,0,0};
    float y0[4] = {0,0,0,0}, y1[4] = {0,0,0,0};
    if (own) {
#pragma unroll
        for (int i = 0; i < 4; ++i) {
            int p = base + r + i * 8;
            if (p < B) {
                float4 z = rin[p];
                x0[i] = z.x; x1[i] = z.y; y0[i] = z.z; y1[i] = z.w;
            }
        }
    }

    u32 B1f[8];

    // ---- inverse psi layers, l = 7 .. 0 ----
    for (int l = 7; l >= 0; --l) {
        {   // load B1 fragment for this layer
            bool hasB1 = (q < 2);
            int i1 = (l * 8) * 16 + q * 8 + r;
#pragma unroll
            for (int j = 0; j < 8; ++j)
                B1f[j] = hasB1 ? sB1[i1 + j * 16] : 0u;
        }
        const uint2* sBgL = &sBg[l * 4 * 8];
        float e0 = seta[l].x, e1 = seta[l].y;
#pragma unroll 1
        for (int k = 0; k < 4; ++k) {
            float yn0[4], yn1[4], G0[4], G1[4];
#pragma unroll
            for (int i = 0; i < 4; ++i) { yn0[i] = x0[i] - e0; yn1[i] = x1[i] - e1; }
            grad_mma(B1f, sBgL, hasBg, idx2, yn0, yn1, own, aconst, G0, G1);
#pragma unroll
            for (int i = 0; i < 4; ++i) {
                float nx0 = G0[i] - y0[i], nx1 = G1[i] - y1[i];
                y0[i] = yn0[i]; y1[i] = yn1[i];
                x0[i] = nx0;    x1[i] = nx1;
            }
        }
    }

    // ---- circle action ----
    {
        float c = scs.x, s = scs.y;
#pragma unroll
        for (int i = 0; i < 4; ++i) {
            float q1 = x0[i], p1 = y0[i];
            x0[i] = fmaf(c, q1, s * p1);
            y0[i] = fmaf(c, p1, -s * q1);
        }
    }

    // ---- forward layers: l = 0..7 psi, l = 8..15 ni ----
    for (int l = 0; l < NLAYERS; ++l) {
        {
            bool hasB1 = (q < 2);
            int i1 = (l * 8) * 16 + q * 8 + r;
#pragma unroll
            for (int j = 0; j < 8; ++j)
                B1f[j] = hasB1 ? sB1[i1 + j * 16] : 0u;
        }
        const uint2* sBgL = &sBg[l * 4 * 8];
        float e0 = seta[l].x, e1 = seta[l].y;
#pragma unroll 1
        for (int k = 0; k < 4; ++k) {
            float G0[4], G1[4];
            grad_mma(B1f, sBgL, hasBg, idx2, y0, y1, own, aconst, G0, G1);
#pragma unroll
            for (int i = 0; i < 4; ++i) {
                float nx0 = y0[i] + e0, nx1 = y1[i] + e1;
                float ny0 = G0[i] - x0[i], ny1 = G1[i] - x1[i];
                x0[i] = nx0; x1[i] = nx1;
                y0[i] = ny0; y1[i] = ny1;
            }
        }
    }

    if (own) {
#pragma unroll
        for (int i = 0; i < 4; ++i) {
            int p = base + r + i * 8;
            if (p < B)
                out[p] = make_float4(x0[i], x1[i], y0[i], y1[i]);
        }
    }
}

extern "C" void kernel_launch(void* const* d_in, const int* in_sizes, int n_in,
                              void* d_out, int out_size)
{
    const float* r        = (const float*)d_in[0];
    const float* theta0   = (const float*)d_in[1];
    const float* psi_Win  = (const float*)d_in[2];
    const float* psi_Wout = (const float*)d_in[3];
    const float* psi_b    = (const float*)d_in[4];
    const float* psi_eta  = (const float*)d_in[5];
    const float* ni_Win   = (const float*)d_in[6];
    const float* ni_Wout  = (const float*)d_in[7];
    const float* ni_b     = (const float*)d_in[8];
    const float* ni_eta   = (const float*)d_in[9];

    int B = in_sizes[0] / 4;
    int nWarps = (B + 31) / 32;

    prep_kernel<<<1, 1024>>>(theta0, psi_Win, psi_Wout, psi_b, psi_eta,
                             ni_Win, ni_Wout, ni_b, ni_eta);

    int blocks = (nWarps + (TPB / 32) - 1) / (TPB / 32);
    gyro_kernel<<<blocks, TPB>>>((const float4*)r, (float4*)d_out, B, nWarps);
}